// round 15
// baseline (speedup 1.0000x reference)
#include <cuda_runtime.h>
#include <cuda_bf16.h>
#include <cstdint>

#define BATCH 4
#define NPTS 8192
#define DFEAT 64
#define SCENT 2048
#define KNEIGH 32
#define EPSBN 1e-5f

#define FPS_CTAS 4
#define KNN_WPB 6                   // KNN workers per batch
#define MLP_WPB 16                  // MLP workers per batch
#define KNN_WORKERS (BATCH * KNN_WPB)   // 24
#define MLP_WORKERS (BATCH * MLP_WPB)   // 64
#define KNN_Q 8                     // queries per KNN chunk
#define MLP_Q 16                    // queries per MLP chunk
#define KNN_CHUNKS 256              // per batch
#define MLP_CHUNKS 128              // per batch
#define FUSED_GRID (FPS_CTAS + KNN_WORKERS + MLP_WORKERS)   // 92 CTAs, 1 wave
#define FUSED_SMEM 117760           // 115 KB -> 1 CTA/SM

// ---------------- scratch (__device__ globals; no allocation allowed) ----------------
__device__ int   g_knn_idx[BATCH * SCENT * KNEIGH];          // 1 MB
__device__ float g_points_t[BATCH * NPTS * DFEAT];           // 8 MB  (B,N,64)
// folded weight blob, TRANSPOSED ([channel][output]) for paired-FMA2 access:
//  [0      .. 4352)  w0T: [c=0..67][o=0..63]   (c*64 + o), c=67 row is zero pad
//  [4352   .. 8448)  w1T: [c=0..63][o=0..63]
//  [8448   ..16640)  w2T: [c=0..63][o=0..127]
//  [16640  .. 16704) bias0   [16704 .. 16768) bias1   [16768 .. 16896) bias2
#define WF_TOTAL 16896
__device__ float g_wfold[WF_TOTAL];
// producer-consumer sync state (reset by init_kernel every launch)
__device__ int g_fps_prog[BATCH];                     // centroids published per batch
__device__ int g_knn_done[BATCH * KNN_CHUNKS];        // per-8-query-chunk flags

// ---------------- f32x2 helpers (bitwise-identical to scalar rn ops) ----------------
__device__ __forceinline__ unsigned long long pk2(float a, float b) {
    unsigned long long r;
    asm("mov.b64 %0, {%1, %2};" : "=l"(r) : "f"(a), "f"(b));
    return r;
}
__device__ __forceinline__ void unpk2(unsigned long long v, float& a, float& b) {
    asm("mov.b64 {%0, %1}, %2;" : "=f"(a), "=f"(b) : "l"(v));
}
__device__ __forceinline__ unsigned long long add2(unsigned long long a, unsigned long long b) {
    unsigned long long r;
    asm("add.rn.f32x2 %0, %1, %2;" : "=l"(r) : "l"(a), "l"(b));
    return r;
}
__device__ __forceinline__ unsigned long long mul2(unsigned long long a, unsigned long long b) {
    unsigned long long r;
    asm("mul.rn.f32x2 %0, %1, %2;" : "=l"(r) : "l"(a), "l"(b));
    return r;
}
__device__ __forceinline__ unsigned long long fma2(unsigned long long a, unsigned long long b,
                                                   unsigned long long c) {
    unsigned long long r;
    asm("fma.rn.f32x2 %0, %1, %2, %3;" : "=l"(r) : "l"(a), "l"(b), "l"(c));
    return r;
}
// ---------------- acquire/release sync helpers ----------------
__device__ __forceinline__ int ld_acq(const int* p) {
    int v;
    asm volatile("ld.acquire.gpu.global.s32 %0, [%1];" : "=r"(v) : "l"(p) : "memory");
    return v;
}
__device__ __forceinline__ void st_rel(int* p, int v) {
    asm volatile("st.release.gpu.global.s32 [%0], %1;" :: "l"(p), "r"(v) : "memory");
}

// ============================================================================
// init kernel: reset sync state (every launch -> deterministic graph replay)
// ============================================================================
__global__ void init_kernel() {
    int t = threadIdx.x;
    if (t < BATCH) g_fps_prog[t] = 0;
    for (int i = t; i < BATCH * KNN_CHUNKS; i += 256) g_knn_done[i] = 0;
}

// ============================================================================
// Kernel 0a: fold BN into weights, store TRANSPOSED ([c][o]) for FMA2 kernels
// ============================================================================
__global__ void fold_kernel(const float* __restrict__ w0, const float* __restrict__ g0,
                            const float* __restrict__ b0, const float* __restrict__ m0,
                            const float* __restrict__ v0,
                            const float* __restrict__ w1, const float* __restrict__ g1,
                            const float* __restrict__ b1, const float* __restrict__ m1,
                            const float* __restrict__ v1,
                            const float* __restrict__ w2, const float* __restrict__ g2,
                            const float* __restrict__ b2, const float* __restrict__ m2,
                            const float* __restrict__ v2) {
    int tid = threadIdx.x, nt = blockDim.x;
    for (int i = tid; i < 68 * 64; i += nt) {
        int c = i >> 6, o = i & 63;
        float s = g0[o] / sqrtf(v0[o] + EPSBN);
        g_wfold[c * 64 + o] = (c < 67) ? w0[o * 67 + c] * s : 0.0f;
    }
    for (int o = tid; o < 64; o += nt) {
        float s = g0[o] / sqrtf(v0[o] + EPSBN);
        g_wfold[16640 + o] = b0[o] - m0[o] * s;
    }
    for (int i = tid; i < 64 * 64; i += nt) {
        int c = i >> 6, o = i & 63;
        float s = g1[o] / sqrtf(v1[o] + EPSBN);
        g_wfold[4352 + c * 64 + o] = w1[o * 64 + c] * s;
    }
    for (int o = tid; o < 64; o += nt) {
        float s = g1[o] / sqrtf(v1[o] + EPSBN);
        g_wfold[16704 + o] = b1[o] - m1[o] * s;
    }
    for (int i = tid; i < 64 * 128; i += nt) {
        int c = i >> 7, o = i & 127;
        float s = g2[o] / sqrtf(v2[o] + EPSBN);
        g_wfold[8448 + c * 128 + o] = w2[o * 64 + c] * s;
    }
    for (int o = tid; o < 128; o += nt) {
        float s = g2[o] / sqrtf(v2[o] + EPSBN);
        g_wfold[16768 + o] = b2[o] - m2[o] * s;
    }
}

// ============================================================================
// Kernel 0b: transpose points (B,64,N) -> (B,N,64)
// ============================================================================
__global__ void transpose_kernel(const float* __restrict__ pts) {
    __shared__ float tl[32][33];
    int b = blockIdx.z;
    int dbase = blockIdx.y * 32;
    int nbase = blockIdx.x * 32;
    const float* src = pts + (size_t)b * DFEAT * NPTS;
    float* dst = g_points_t + (size_t)b * NPTS * DFEAT;
    int tx = threadIdx.x, ty = threadIdx.y;
#pragma unroll
    for (int r = ty; r < 32; r += 8)
        tl[r][tx] = src[(size_t)(dbase + r) * NPTS + nbase + tx];
    __syncthreads();
#pragma unroll
    for (int r = ty; r < 32; r += 8)
        dst[(size_t)(nbase + r) * DFEAT + dbase + tx] = tl[tx][r];
}

// ============================================================================
// FPS role (blocks 0..3): 256 threads x 32 strided pts (R8-measured variant).
// Publishes per-batch centroid progress every 32 iterations (st.release).
// rn mul/add via f32x2 (bitwise == scalar rn): trajectory bitwise == XLA.
// ============================================================================
#define FPS_T 256
__device__ void fps_role(const float* __restrict__ xyz, float* __restrict__ out_newxyz,
                         int b) {
    extern __shared__ float smf[];
    float* sxp = smf;
    float* syp = smf + NPTS;
    float* szp = smf + 2 * NPTS;
    const int t = threadIdx.x;
    const int lane = t & 31, wid = t >> 5;
    const float* px = xyz + (size_t)b * NPTS * 3;
    float* onx = out_newxyz + (size_t)b * SCENT * 3;

    unsigned long long Xp[16], Yp[16], Zp[16];
    float D[32];
#pragma unroll
    for (int p = 0; p < 16; p++) {
        int i0 = (2 * p) * FPS_T + t;
        int i1 = i0 + FPS_T;
        float x0 = px[i0 * 3 + 0], y0 = px[i0 * 3 + 1], z0 = px[i0 * 3 + 2];
        float x1 = px[i1 * 3 + 0], y1 = px[i1 * 3 + 1], z1 = px[i1 * 3 + 2];
        sxp[i0] = x0; syp[i0] = y0; szp[i0] = z0;
        sxp[i1] = x1; syp[i1] = y1; szp[i1] = z1;
        Xp[p] = pk2(x0, x1);
        Yp[p] = pk2(y0, y1);
        Zp[p] = pk2(z0, z1);
        D[2 * p] = 1e10f;
        D[2 * p + 1] = 1e10f;
    }

    __shared__ unsigned s_wv[2][8];
    __shared__ int s_best[2];
    if (t == 0) { s_best[0] = 0x7fffffff; s_best[1] = 0x7fffffff; }
    __syncthreads();

    int far = 0;
    for (int it = 0; it < SCENT; ++it) {
        float cx = sxp[far];
        float cy = syp[far];
        float cz = szp[far];
        if (t == 0) {
            onx[it * 3 + 0] = cx;
            onx[it * 3 + 1] = cy;
            onx[it * 3 + 2] = cz;
            if ((it & 31) == 31) st_rel(&g_fps_prog[b], it + 1);
        }
        unsigned long long ncx = pk2(-cx, -cx);
        unsigned long long ncy = pk2(-cy, -cy);
        unsigned long long ncz = pk2(-cz, -cz);

        float lm = -1.0f;
#pragma unroll
        for (int p = 0; p < 16; p++) {
            unsigned long long dx = add2(Xp[p], ncx);
            unsigned long long dy = add2(Yp[p], ncy);
            unsigned long long dz = add2(Zp[p], ncz);
            unsigned long long sx = mul2(dx, dx);
            unsigned long long sy = mul2(dy, dy);
            unsigned long long sz = mul2(dz, dz);
            unsigned long long dd = add2(add2(sx, sy), sz);
            float dlo, dhi;
            unpk2(dd, dlo, dhi);
            D[2 * p]     = fminf(D[2 * p], dlo);
            D[2 * p + 1] = fminf(D[2 * p + 1], dhi);
            lm = fmaxf(lm, D[2 * p]);
            lm = fmaxf(lm, D[2 * p + 1]);
        }

        unsigned lmb = __float_as_uint(lm);
        unsigned wm = __reduce_max_sync(0xffffffffu, lmb);
        if (lane == 0) s_wv[it & 1][wid] = wm;
        __syncthreads();
        unsigned gmb = __reduce_max_sync(0xffffffffu, s_wv[it & 1][lane & 7]);
        float gm = __uint_as_float(gmb);

        if (t == 0) s_best[(it + 1) & 1] = 0x7fffffff;
        if (lmb == wm && wm == gmb) {
            int best = 0x7fffffff;
#pragma unroll
            for (int k = 31; k >= 0; k--)
                if (D[k] == gm) best = k * FPS_T + t;
            atomicMin(&s_best[it & 1], best);
        }
        __syncthreads();
        far = s_best[it & 1];
    }
    // final publish (covers any consumer still waiting on the last batch)
    if (t == 0) st_rel(&g_fps_prog[b], SCENT);
}

// ============================================================================
// KNN worker (persistent): 6 workers per batch; worker handles chunks
// off, off+6, ... (8 queries each, one warp per query) in increasing order,
// pacing with FPS progress. Batch point cloud loaded to smem ONCE.
// ============================================================================
__device__ void knn_worker(const float* __restrict__ xyz, const float* __restrict__ newxyz,
                           int w) {
    extern __shared__ float sm[];
    float* sx = sm;
    float* sy = sm + NPTS;
    float* sz = sm + 2 * NPTS;
    const int b = w & 3;
    const int off = w >> 2;                 // 0..5
    const float* px = xyz + (size_t)b * NPTS * 3;

    for (int i = threadIdx.x; i < NPTS; i += 256) {
        float x = px[3 * i], y = px[3 * i + 1], z = px[3 * i + 2];
        sx[i] = x; sy[i] = y; sz[i] = z;
    }
    __syncthreads();

    const int lane = threadIdx.x & 31, wid = threadIdx.x >> 5;

    for (int j = off; j < KNN_CHUNKS; j += KNN_WPB) {
        if (threadIdx.x == 0) {
            while (ld_acq(&g_fps_prog[b]) < j * KNN_Q + KNN_Q) __nanosleep(256);
        }
        __syncthreads();

        const int g = b * SCENT + j * KNN_Q + wid;
        const float qx = newxyz[3 * g], qy = newxyz[3 * g + 1], qz = newxyz[3 * g + 2];

        float d;
        int id;
        {
            float dx = qx - sx[lane], dy = qy - sy[lane], dz = qz - sz[lane];
            d = fmaf(dx, dx, fmaf(dy, dy, dz * dz));
            id = lane;
        }
#pragma unroll
        for (int k = 2; k <= 32; k <<= 1) {
#pragma unroll
            for (int jj = k >> 1; jj; jj >>= 1) {
                float od = __shfl_xor_sync(0xffffffffu, d, jj);
                int oi = __shfl_xor_sync(0xffffffffu, id, jj);
                bool up = ((lane & k) == 0);
                bool lower = ((lane & jj) == 0);
                bool take = lower ? (up ? (od < d) : (od > d)) : (up ? (od > d) : (od < d));
                if (take) { d = od; id = oi; }
            }
        }
        float th = __shfl_sync(0xffffffffu, d, 31);

        for (int base = 32; base < NPTS; base += 32) {
            int jdx = base + lane;
            float dx = qx - sx[jdx], dy = qy - sy[jdx], dz = qz - sz[jdx];
            float dj = fmaf(dx, dx, fmaf(dy, dy, dz * dz));
            unsigned mask = __ballot_sync(0xffffffffu, dj < th);
            while (mask) {
                int src = __ffs(mask) - 1;
                mask &= mask - 1;
                float dc = __shfl_sync(0xffffffffu, dj, src);
                int ic = base + src;
                if (dc < th) {
                    float ud = __shfl_up_sync(0xffffffffu, d, 1);
                    int ui = __shfl_up_sync(0xffffffffu, id, 1);
                    bool gt = d > dc;
                    bool ugt = (lane > 0) && (ud > dc);
                    if (gt) {
                        if (ugt) { d = ud; id = ui; }
                        else     { d = dc; id = ic; }
                    }
                    th = __shfl_sync(0xffffffffu, d, 31);
                }
            }
        }
        g_knn_idx[(size_t)g * KNEIGH + lane] = id;

        __threadfence();
        __syncthreads();
        if (threadIdx.x == 0) st_rel(&g_knn_done[b * KNN_CHUNKS + j], 1);
    }
}

// ============================================================================
// MLP worker (persistent): 16 workers per batch; worker handles chunks
// off, off+16, ... (16 queries each, 2 per warp). Weights loaded ONCE.
// ============================================================================
__device__ void mlp_worker(const float* __restrict__ xyz, const float* __restrict__ newxyz,
                           float* __restrict__ outp, int w) {
    extern __shared__ float sm[];
    {
        const float4* srcv = (const float4*)g_wfold;
        float4* dstv = (float4*)sm;
        for (int i = threadIdx.x; i < WF_TOTAL / 4; i += 256) dstv[i] = srcv[i];
    }
    float* otile = sm + WF_TOTAL;  // [128][16]
    __syncthreads();

    const int b = w & 3;
    const int off = w >> 2;        // 0..15
    const int lane = threadIdx.x & 31, wid = threadIdx.x >> 5;

    for (int j = off; j < MLP_CHUNKS; j += MLP_WPB) {
        if (threadIdx.x == 0) {
            while (ld_acq(&g_knn_done[b * KNN_CHUNKS + 2 * j]) == 0) __nanosleep(256);
            while (ld_acq(&g_knn_done[b * KNN_CHUNKS + 2 * j + 1]) == 0) __nanosleep(256);
        }
        __syncthreads();

#pragma unroll 1
        for (int jj = 0; jj < 2; jj++) {
            const int qc = wid * 2 + jj;
            const int g = b * SCENT + j * MLP_Q + qc;
            const float qx = newxyz[3 * g], qy = newxyz[3 * g + 1], qz = newxyz[3 * g + 2];

            const int n = g_knn_idx[(size_t)g * KNEIGH + lane];
            const float* p = xyz + ((size_t)b * NPTS + n) * 3;

            float in0[68];
            in0[0] = p[0] - qx;
            in0[1] = p[1] - qy;
            in0[2] = p[2] - qz;
            const float4* fr = (const float4*)(g_points_t + ((size_t)b * NPTS + n) * DFEAT);
#pragma unroll
            for (int c = 0; c < 16; c++) {
                float4 v = __ldg(fr + c);
                in0[3 + 4 * c] = v.x;
                in0[4 + 4 * c] = v.y;
                in0[5 + 4 * c] = v.z;
                in0[6 + 4 * c] = v.w;
            }
            in0[67] = 0.0f;

            unsigned long long acc[32];

#pragma unroll
            for (int o2 = 0; o2 < 32; o2++)
                acc[o2] = *(const unsigned long long*)(sm + 16640 + 2 * o2);
#pragma unroll
            for (int c = 0; c < 68; c++) {
                unsigned long long inp = pk2(in0[c], in0[c]);
                const ulonglong2* wrow = (const ulonglong2*)(sm + c * 64);
#pragma unroll
                for (int gq = 0; gq < 16; gq++) {
                    ulonglong2 wv = wrow[gq];
                    acc[2 * gq]     = fma2(inp, wv.x, acc[2 * gq]);
                    acc[2 * gq + 1] = fma2(inp, wv.y, acc[2 * gq + 1]);
                }
            }
            float h1[64];
#pragma unroll
            for (int o2 = 0; o2 < 32; o2++) {
                float lo, hi;
                unpk2(acc[o2], lo, hi);
                h1[2 * o2] = fmaxf(lo, 0.0f);
                h1[2 * o2 + 1] = fmaxf(hi, 0.0f);
            }

#pragma unroll
            for (int o2 = 0; o2 < 32; o2++)
                acc[o2] = *(const unsigned long long*)(sm + 16704 + 2 * o2);
#pragma unroll
            for (int c = 0; c < 64; c++) {
                unsigned long long inp = pk2(h1[c], h1[c]);
                const ulonglong2* wrow = (const ulonglong2*)(sm + 4352 + c * 64);
#pragma unroll
                for (int gq = 0; gq < 16; gq++) {
                    ulonglong2 wv = wrow[gq];
                    acc[2 * gq]     = fma2(inp, wv.x, acc[2 * gq]);
                    acc[2 * gq + 1] = fma2(inp, wv.y, acc[2 * gq + 1]);
                }
            }
            float h2[64];
#pragma unroll
            for (int o2 = 0; o2 < 32; o2++) {
                float lo, hi;
                unpk2(acc[o2], lo, hi);
                h2[2 * o2] = fmaxf(lo, 0.0f);
                h2[2 * o2 + 1] = fmaxf(hi, 0.0f);
            }

#pragma unroll 1
            for (int h = 0; h < 2; h++) {
#pragma unroll
                for (int o2 = 0; o2 < 32; o2++)
                    acc[o2] = *(const unsigned long long*)(sm + 16768 + h * 64 + 2 * o2);
#pragma unroll
                for (int c = 0; c < 64; c++) {
                    unsigned long long inp = pk2(h2[c], h2[c]);
                    const ulonglong2* wrow = (const ulonglong2*)(sm + 8448 + c * 128 + h * 64);
#pragma unroll
                    for (int gq = 0; gq < 16; gq++) {
                        ulonglong2 wv = wrow[gq];
                        acc[2 * gq]     = fma2(inp, wv.x, acc[2 * gq]);
                        acc[2 * gq + 1] = fma2(inp, wv.y, acc[2 * gq + 1]);
                    }
                }
#pragma unroll
                for (int o2 = 0; o2 < 32; o2++) {
                    float lo, hi;
                    unpk2(acc[o2], lo, hi);
                    float rlo = fmaxf(lo, 0.0f);
                    float rhi = fmaxf(hi, 0.0f);
                    unsigned ulo = __reduce_max_sync(0xffffffffu, __float_as_uint(rlo));
                    unsigned uhi = __reduce_max_sync(0xffffffffu, __float_as_uint(rhi));
                    if (lane == 0) {
                        otile[(h * 64 + 2 * o2) * MLP_Q + qc] = __uint_as_float(ulo);
                        otile[(h * 64 + 2 * o2 + 1) * MLP_Q + qc] = __uint_as_float(uhi);
                    }
                }
            }
        }
        __syncthreads();
        const int sbase = j * MLP_Q;
        for (int i = threadIdx.x; i < 128 * MLP_Q; i += 256) {
            int o = i / MLP_Q, qc = i - o * MLP_Q;
            outp[((size_t)b * 128 + o) * SCENT + sbase + qc] = otile[i];
        }
        __syncthreads();  // otile reused next chunk
    }
}

// ============================================================================
// Fused persistent kernel: 92 CTAs (1 CTA/SM @ 115 KB), 56 SMs left idle to
// keep clocks high for the serial FPS chain.
// ============================================================================
__global__ void __launch_bounds__(256) fused_kernel(const float* __restrict__ xyz,
                                                    float* __restrict__ newxyz,
                                                    float* __restrict__ newpts) {
    const int bid = blockIdx.x;
    if (bid < FPS_CTAS) {
        fps_role(xyz, newxyz, bid);
    } else if (bid < FPS_CTAS + KNN_WORKERS) {
        knn_worker(xyz, newxyz, bid - FPS_CTAS);
    } else {
        mlp_worker(xyz, newxyz, newpts, bid - FPS_CTAS - KNN_WORKERS);
    }
}

// ============================================================================
// Launch
// ============================================================================
extern "C" void kernel_launch(void* const* d_in, const int* in_sizes, int n_in,
                              void* d_out, int out_size) {
    const float* xyz = (const float*)d_in[0];
    const float* points = (const float*)d_in[1];
    const float* w0 = (const float*)d_in[2];
    const float* g0 = (const float*)d_in[3];
    const float* b0 = (const float*)d_in[4];
    const float* m0 = (const float*)d_in[5];
    const float* v0 = (const float*)d_in[6];
    const float* w1 = (const float*)d_in[7];
    const float* g1 = (const float*)d_in[8];
    const float* b1 = (const float*)d_in[9];
    const float* m1 = (const float*)d_in[10];
    const float* v1 = (const float*)d_in[11];
    const float* w2 = (const float*)d_in[12];
    const float* g2 = (const float*)d_in[13];
    const float* b2 = (const float*)d_in[14];
    const float* m2 = (const float*)d_in[15];
    const float* v2 = (const float*)d_in[16];

    float* out = (float*)d_out;
    float* newxyz = out;                              // (B,S,3)
    float* newpts = out + (size_t)BATCH * SCENT * 3;  // (B,128,S)

    cudaFuncSetAttribute(fused_kernel, cudaFuncAttributeMaxDynamicSharedMemorySize,
                         FUSED_SMEM);

    init_kernel<<<1, 256>>>();
    fold_kernel<<<1, 512>>>(w0, g0, b0, m0, v0, w1, g1, b1, m1, v1, w2, g2, b2, m2, v2);
    transpose_kernel<<<dim3(NPTS / 32, DFEAT / 32, BATCH), dim3(32, 8)>>>(points);
    fused_kernel<<<FUSED_GRID, 256, FUSED_SMEM>>>(xyz, newxyz, newpts);
}

// round 16
// speedup vs baseline: 1.1335x; 1.1335x over previous
#include <cuda_runtime.h>
#include <cuda_bf16.h>
#include <cstdint>

#define BATCH 4
#define NPTS 8192
#define DFEAT 64
#define SCENT 2048
#define KNEIGH 32
#define EPSBN 1e-5f

// ---------------- scratch (__device__ globals; no allocation allowed) ----------------
__device__ int   g_knn_idx[BATCH * SCENT * KNEIGH];          // 1 MB
__device__ float g_points_t[BATCH * NPTS * DFEAT];           // 8 MB  (B,N,64)
// folded weight blob, TRANSPOSED ([channel][output]) for paired-FMA2 access:
//  [0      .. 4352)  w0T: [c=0..67][o=0..63]   (c*64 + o), c=67 row is zero pad
//  [4352   .. 8448)  w1T: [c=0..63][o=0..63]   (4352 + c*64 + o)
//  [8448   ..16640)  w2T: [c=0..63][o=0..127]  (8448 + c*128 + o)
//  [16640  .. 16704) bias0 (64)
//  [16704  .. 16768) bias1 (64)
//  [16768  .. 16896) bias2 (128)
#define WF_TOTAL 16896
__device__ float g_wfold[WF_TOTAL];
// persistent-MLP work counter (reset every launch by init_kernel)
__device__ int g_mlp_ctr;

#define MLP_Q_PER_CTA 16
#define MLP_CHUNKS (BATCH * SCENT / MLP_Q_PER_CTA)   // 512
#define MLP_GRID 148

// ---------------- f32x2 helpers (bitwise-identical to scalar rn ops) ----------------
__device__ __forceinline__ unsigned long long pk2(float a, float b) {
    unsigned long long r;
    asm("mov.b64 %0, {%1, %2};" : "=l"(r) : "f"(a), "f"(b));
    return r;
}
__device__ __forceinline__ void unpk2(unsigned long long v, float& a, float& b) {
    asm("mov.b64 {%0, %1}, %2;" : "=f"(a), "=f"(b) : "l"(v));
}
__device__ __forceinline__ unsigned long long add2(unsigned long long a, unsigned long long b) {
    unsigned long long r;
    asm("add.rn.f32x2 %0, %1, %2;" : "=l"(r) : "l"(a), "l"(b));
    return r;
}
__device__ __forceinline__ unsigned long long mul2(unsigned long long a, unsigned long long b) {
    unsigned long long r;
    asm("mul.rn.f32x2 %0, %1, %2;" : "=l"(r) : "l"(a), "l"(b));
    return r;
}
__device__ __forceinline__ unsigned long long fma2(unsigned long long a, unsigned long long b,
                                                   unsigned long long c) {
    unsigned long long r;
    asm("fma.rn.f32x2 %0, %1, %2, %3;" : "=l"(r) : "l"(a), "l"(b), "l"(c));
    return r;
}

// ============================================================================
// init kernel: reset MLP work counter (deterministic graph replay)
// ============================================================================
__global__ void init_kernel() {
    if (threadIdx.x == 0) g_mlp_ctr = 0;
}

// ============================================================================
// Kernel 0a: fold BN into weights, store TRANSPOSED ([c][o]) for FMA2 kernels
// ============================================================================
__global__ void fold_kernel(const float* __restrict__ w0, const float* __restrict__ g0,
                            const float* __restrict__ b0, const float* __restrict__ m0,
                            const float* __restrict__ v0,
                            const float* __restrict__ w1, const float* __restrict__ g1,
                            const float* __restrict__ b1, const float* __restrict__ m1,
                            const float* __restrict__ v1,
                            const float* __restrict__ w2, const float* __restrict__ g2,
                            const float* __restrict__ b2, const float* __restrict__ m2,
                            const float* __restrict__ v2) {
    int tid = threadIdx.x, nt = blockDim.x;
    for (int i = tid; i < 68 * 64; i += nt) {
        int c = i >> 6, o = i & 63;
        float s = g0[o] / sqrtf(v0[o] + EPSBN);
        g_wfold[c * 64 + o] = (c < 67) ? w0[o * 67 + c] * s : 0.0f;
    }
    for (int o = tid; o < 64; o += nt) {
        float s = g0[o] / sqrtf(v0[o] + EPSBN);
        g_wfold[16640 + o] = b0[o] - m0[o] * s;
    }
    for (int i = tid; i < 64 * 64; i += nt) {
        int c = i >> 6, o = i & 63;
        float s = g1[o] / sqrtf(v1[o] + EPSBN);
        g_wfold[4352 + c * 64 + o] = w1[o * 64 + c] * s;
    }
    for (int o = tid; o < 64; o += nt) {
        float s = g1[o] / sqrtf(v1[o] + EPSBN);
        g_wfold[16704 + o] = b1[o] - m1[o] * s;
    }
    for (int i = tid; i < 64 * 128; i += nt) {
        int c = i >> 7, o = i & 127;
        float s = g2[o] / sqrtf(v2[o] + EPSBN);
        g_wfold[8448 + c * 128 + o] = w2[o * 64 + c] * s;
    }
    for (int o = tid; o < 128; o += nt) {
        float s = g2[o] / sqrtf(v2[o] + EPSBN);
        g_wfold[16768 + o] = b2[o] - m2[o] * s;
    }
}

// ============================================================================
// Kernel 0b: transpose points (B,64,N) -> (B,N,64)
// ============================================================================
__global__ void transpose_kernel(const float* __restrict__ pts) {
    __shared__ float tl[32][33];
    int b = blockIdx.z;
    int dbase = blockIdx.y * 32;
    int nbase = blockIdx.x * 32;
    const float* src = pts + (size_t)b * DFEAT * NPTS;
    float* dst = g_points_t + (size_t)b * NPTS * DFEAT;
    int tx = threadIdx.x, ty = threadIdx.y;
#pragma unroll
    for (int r = ty; r < 32; r += 8)
        tl[r][tx] = src[(size_t)(dbase + r) * NPTS + nbase + tx];
    __syncthreads();
#pragma unroll
    for (int r = ty; r < 32; r += 8)
        dst[(size_t)(nbase + r) * DFEAT + dbase + tx] = tl[tx][r];
}

// ============================================================================
// Kernel 1: farthest point sampling — exact R6/R9 winner (best measured):
// 512 threads x 16 strided pts, packed add2/mul2 distance math, scalar
// fminf/fmaxf, SMEM coords (no LDG on critical path), REDUX two-stage
// reduction, atomicMin tie-break, two barriers.
// rn mul/add via f32x2 (bitwise == scalar rn): trajectory bitwise == XLA.
// ============================================================================
__global__ void __launch_bounds__(512) fps_kernel(const float* __restrict__ xyz,
                                                  float* __restrict__ out_newxyz) {
    extern __shared__ float smf[];
    float* sxp = smf;              // [8192]
    float* syp = smf + NPTS;       // [8192]
    float* szp = smf + 2 * NPTS;   // [8192]
    const int b = blockIdx.x, t = threadIdx.x;
    const int lane = t & 31, wid = t >> 5;
    const float* px = xyz + (size_t)b * NPTS * 3;
    float* onx = out_newxyz + (size_t)b * SCENT * 3;

    unsigned long long Xp[8], Yp[8], Zp[8];
    float D[16];
#pragma unroll
    for (int p = 0; p < 8; p++) {
        int i0 = (2 * p) * 512 + t;
        int i1 = i0 + 512;
        float x0 = px[i0 * 3 + 0], y0 = px[i0 * 3 + 1], z0 = px[i0 * 3 + 2];
        float x1 = px[i1 * 3 + 0], y1 = px[i1 * 3 + 1], z1 = px[i1 * 3 + 2];
        sxp[i0] = x0; syp[i0] = y0; szp[i0] = z0;
        sxp[i1] = x1; syp[i1] = y1; szp[i1] = z1;
        Xp[p] = pk2(x0, x1);
        Yp[p] = pk2(y0, y1);
        Zp[p] = pk2(z0, z1);
        D[2 * p] = 1e10f;
        D[2 * p + 1] = 1e10f;
    }

    __shared__ unsigned s_wv[2][16];
    __shared__ int s_best[2];
    if (t == 0) { s_best[0] = 0x7fffffff; s_best[1] = 0x7fffffff; }
    __syncthreads();

    int far = 0;
    for (int it = 0; it < SCENT; ++it) {
        float cx = sxp[far];
        float cy = syp[far];
        float cz = szp[far];
        if (t == 0) {
            onx[it * 3 + 0] = cx;
            onx[it * 3 + 1] = cy;
            onx[it * 3 + 2] = cz;
        }
        unsigned long long ncx = pk2(-cx, -cx);
        unsigned long long ncy = pk2(-cy, -cy);
        unsigned long long ncz = pk2(-cz, -cz);

#pragma unroll
        for (int p = 0; p < 8; p++) {
            unsigned long long dx = add2(Xp[p], ncx);
            unsigned long long dy = add2(Yp[p], ncy);
            unsigned long long dz = add2(Zp[p], ncz);
            unsigned long long sx = mul2(dx, dx);
            unsigned long long sy = mul2(dy, dy);
            unsigned long long sz = mul2(dz, dz);
            unsigned long long dd = add2(add2(sx, sy), sz);
            float dlo, dhi;
            unpk2(dd, dlo, dhi);
            D[2 * p]     = fminf(D[2 * p], dlo);
            D[2 * p + 1] = fminf(D[2 * p + 1], dhi);
        }
        float lm = -1.0f;
#pragma unroll
        for (int k = 0; k < 16; k++) lm = fmaxf(lm, D[k]);

        // warp max via REDUX (distances >= 0 so uint order == float order)
        unsigned lmb = __float_as_uint(lm);
        unsigned wm = __reduce_max_sync(0xffffffffu, lmb);
        if (lane == 0) s_wv[it & 1][wid] = wm;
        __syncthreads();
        // every warp reduces the 16 leader values -> no serial warp0 phase
        unsigned gmb = __reduce_max_sync(0xffffffffu, s_wv[it & 1][lane & 15]);
        float gm = __uint_as_float(gmb);

        if (t == 0) s_best[(it + 1) & 1] = 0x7fffffff;  // reset next slot
        if (lmb == wm && wm == gmb) {
            int best = 0x7fffffff;
#pragma unroll
            for (int k = 15; k >= 0; k--)
                if (D[k] == gm) best = k * 512 + t;
            atomicMin(&s_best[it & 1], best);
        }
        __syncthreads();
        far = s_best[it & 1];
    }
}

// ============================================================================
// Kernel 2: KNN. One warp per query, 32 queries/CTA (1024 threads). Batch xyz
// (SoA) in 96 KB SMEM; warp-distributed sorted top-32 list with threshold
// reject. Exact R9 winner.
// ============================================================================
__global__ void __launch_bounds__(1024) knn_kernel(const float* __restrict__ xyz,
                                                   const float* __restrict__ newxyz) {
    extern __shared__ float sm[];
    float* sx = sm;
    float* sy = sm + NPTS;
    float* sz = sm + 2 * NPTS;
    const int b = blockIdx.x >> 6;              // 64 CTAs per batch
    const int sbase = (blockIdx.x & 63) * 32;   // 32 queries per CTA
    const float* px = xyz + (size_t)b * NPTS * 3;

    for (int i = threadIdx.x; i < NPTS; i += 1024) {
        float x = px[3 * i], y = px[3 * i + 1], z = px[3 * i + 2];
        sx[i] = x; sy[i] = y; sz[i] = z;
    }
    __syncthreads();

    const int lane = threadIdx.x & 31, wid = threadIdx.x >> 5;
    const int g = b * SCENT + sbase + wid;
    const float qx = newxyz[3 * g], qy = newxyz[3 * g + 1], qz = newxyz[3 * g + 2];

    float d;
    int id;
    {
        float dx = qx - sx[lane], dy = qy - sy[lane], dz = qz - sz[lane];
        d = fmaf(dx, dx, fmaf(dy, dy, dz * dz));
        id = lane;
    }
    // bitonic sort ascending across warp
#pragma unroll
    for (int k = 2; k <= 32; k <<= 1) {
#pragma unroll
        for (int jj = k >> 1; jj; jj >>= 1) {
            float od = __shfl_xor_sync(0xffffffffu, d, jj);
            int oi = __shfl_xor_sync(0xffffffffu, id, jj);
            bool up = ((lane & k) == 0);
            bool lower = ((lane & jj) == 0);
            bool take = lower ? (up ? (od < d) : (od > d)) : (up ? (od > d) : (od < d));
            if (take) { d = od; id = oi; }
        }
    }
    float th = __shfl_sync(0xffffffffu, d, 31);

    for (int base = 32; base < NPTS; base += 32) {
        int jdx = base + lane;
        float dx = qx - sx[jdx], dy = qy - sy[jdx], dz = qz - sz[jdx];
        float dj = fmaf(dx, dx, fmaf(dy, dy, dz * dz));
        unsigned mask = __ballot_sync(0xffffffffu, dj < th);
        while (mask) {
            int src = __ffs(mask) - 1;
            mask &= mask - 1;
            float dc = __shfl_sync(0xffffffffu, dj, src);
            int ic = base + src;
            if (dc < th) {
                float ud = __shfl_up_sync(0xffffffffu, d, 1);
                int ui = __shfl_up_sync(0xffffffffu, id, 1);
                bool gt = d > dc;
                bool ugt = (lane > 0) && (ud > dc);
                if (gt) {
                    if (ugt) { d = ud; id = ui; }
                    else     { d = dc; id = ic; }
                }
                th = __shfl_sync(0xffffffffu, d, 31);
            }
        }
    }
    g_knn_idx[(size_t)g * KNEIGH + lane] = id;
}

// ============================================================================
// Kernel 3: PERSISTENT gather + fused MLP(67->64->64->128) + max over K.
// Grid = 148 CTAs; chunks of 16 queries distributed by atomicAdd counter
// (no wave quantization; weights loaded once per CTA). Chunk output is
// independent of which CTA computes it -> results bitwise identical to the
// static-grid version. Body numerics identical to the R9 winner.
// ============================================================================
__global__ void __launch_bounds__(256) mlp_kernel(const float* __restrict__ xyz,
                                                  const float* __restrict__ newxyz,
                                                  float* __restrict__ outp) {
    extern __shared__ float sm[];
    {
        const float4* srcv = (const float4*)g_wfold;
        float4* dstv = (float4*)sm;
        for (int i = threadIdx.x; i < WF_TOTAL / 4; i += 256) dstv[i] = srcv[i];
    }
    float* otile = sm + WF_TOTAL;  // [128][16]
    __shared__ int s_chunk;
    __syncthreads();

    const int lane = threadIdx.x & 31, wid = threadIdx.x >> 5;

    while (true) {
        if (threadIdx.x == 0) s_chunk = atomicAdd(&g_mlp_ctr, 1);
        __syncthreads();
        const int mb = s_chunk;
        if (mb >= MLP_CHUNKS) break;

#pragma unroll 1
        for (int j = 0; j < 2; j++) {
            const int qc = wid * 2 + j;
            const int g = mb * MLP_Q_PER_CTA + qc;
            const int b = g >> 11;
            const float qx = newxyz[3 * g], qy = newxyz[3 * g + 1], qz = newxyz[3 * g + 2];

            const int n = g_knn_idx[(size_t)g * KNEIGH + lane];
            const float* p = xyz + ((size_t)b * NPTS + n) * 3;

            float in0[68];
            in0[0] = p[0] - qx;
            in0[1] = p[1] - qy;
            in0[2] = p[2] - qz;
            const float4* fr = (const float4*)(g_points_t + ((size_t)b * NPTS + n) * DFEAT);
#pragma unroll
            for (int c = 0; c < 16; c++) {
                float4 v = __ldg(fr + c);
                in0[3 + 4 * c] = v.x;
                in0[4 + 4 * c] = v.y;
                in0[5 + 4 * c] = v.z;
                in0[6 + 4 * c] = v.w;
            }
            in0[67] = 0.0f;

            unsigned long long acc[32];

            // ---- layer 0: 68 channels (incl. zero pad) -> 64 outputs ----
#pragma unroll
            for (int o2 = 0; o2 < 32; o2++)
                acc[o2] = *(const unsigned long long*)(sm + 16640 + 2 * o2);
#pragma unroll
            for (int c = 0; c < 68; c++) {
                unsigned long long inp = pk2(in0[c], in0[c]);
                const ulonglong2* wrow = (const ulonglong2*)(sm + c * 64);
#pragma unroll
                for (int gq = 0; gq < 16; gq++) {
                    ulonglong2 w = wrow[gq];
                    acc[2 * gq]     = fma2(inp, w.x, acc[2 * gq]);
                    acc[2 * gq + 1] = fma2(inp, w.y, acc[2 * gq + 1]);
                }
            }
            float h1[64];
#pragma unroll
            for (int o2 = 0; o2 < 32; o2++) {
                float lo, hi;
                unpk2(acc[o2], lo, hi);
                h1[2 * o2] = fmaxf(lo, 0.0f);
                h1[2 * o2 + 1] = fmaxf(hi, 0.0f);
            }

            // ---- layer 1: 64 -> 64 ----
#pragma unroll
            for (int o2 = 0; o2 < 32; o2++)
                acc[o2] = *(const unsigned long long*)(sm + 16704 + 2 * o2);
#pragma unroll
            for (int c = 0; c < 64; c++) {
                unsigned long long inp = pk2(h1[c], h1[c]);
                const ulonglong2* wrow = (const ulonglong2*)(sm + 4352 + c * 64);
#pragma unroll
                for (int gq = 0; gq < 16; gq++) {
                    ulonglong2 w = wrow[gq];
                    acc[2 * gq]     = fma2(inp, w.x, acc[2 * gq]);
                    acc[2 * gq + 1] = fma2(inp, w.y, acc[2 * gq + 1]);
                }
            }
            float h2[64];
#pragma unroll
            for (int o2 = 0; o2 < 32; o2++) {
                float lo, hi;
                unpk2(acc[o2], lo, hi);
                h2[2 * o2] = fmaxf(lo, 0.0f);
                h2[2 * o2 + 1] = fmaxf(hi, 0.0f);
            }

            // ---- layer 2: 64 -> 128, two halves of 64 outputs ----
#pragma unroll 1
            for (int h = 0; h < 2; h++) {
#pragma unroll
                for (int o2 = 0; o2 < 32; o2++)
                    acc[o2] = *(const unsigned long long*)(sm + 16768 + h * 64 + 2 * o2);
#pragma unroll
                for (int c = 0; c < 64; c++) {
                    unsigned long long inp = pk2(h2[c], h2[c]);
                    const ulonglong2* wrow = (const ulonglong2*)(sm + 8448 + c * 128 + h * 64);
#pragma unroll
                    for (int gq = 0; gq < 16; gq++) {
                        ulonglong2 w = wrow[gq];
                        acc[2 * gq]     = fma2(inp, w.x, acc[2 * gq]);
                        acc[2 * gq + 1] = fma2(inp, w.y, acc[2 * gq + 1]);
                    }
                }
#pragma unroll
                for (int o2 = 0; o2 < 32; o2++) {
                    float lo, hi;
                    unpk2(acc[o2], lo, hi);
                    float rlo = fmaxf(lo, 0.0f);
                    float rhi = fmaxf(hi, 0.0f);
                    // post-ReLU >= 0: uint order == float order
                    unsigned ulo = __reduce_max_sync(0xffffffffu, __float_as_uint(rlo));
                    unsigned uhi = __reduce_max_sync(0xffffffffu, __float_as_uint(rhi));
                    if (lane == 0) {
                        otile[(h * 64 + 2 * o2) * MLP_Q_PER_CTA + qc] = __uint_as_float(ulo);
                        otile[(h * 64 + 2 * o2 + 1) * MLP_Q_PER_CTA + qc] = __uint_as_float(uhi);
                    }
                }
            }
        }
        __syncthreads();
        const int g0 = mb * MLP_Q_PER_CTA;
        const int b = g0 >> 11;
        const int sbase = g0 & 2047;
        for (int i = threadIdx.x; i < 128 * MLP_Q_PER_CTA; i += 256) {
            int o = i / MLP_Q_PER_CTA, qc = i - o * MLP_Q_PER_CTA;
            outp[((size_t)b * 128 + o) * SCENT + sbase + qc] = otile[i];
        }
        __syncthreads();  // otile reused next chunk
    }
}

// ============================================================================
// Launch
// ============================================================================
extern "C" void kernel_launch(void* const* d_in, const int* in_sizes, int n_in,
                              void* d_out, int out_size) {
    const float* xyz = (const float*)d_in[0];
    const float* points = (const float*)d_in[1];
    const float* w0 = (const float*)d_in[2];
    const float* g0 = (const float*)d_in[3];
    const float* b0 = (const float*)d_in[4];
    const float* m0 = (const float*)d_in[5];
    const float* v0 = (const float*)d_in[6];
    const float* w1 = (const float*)d_in[7];
    const float* g1 = (const float*)d_in[8];
    const float* b1 = (const float*)d_in[9];
    const float* m1 = (const float*)d_in[10];
    const float* v1 = (const float*)d_in[11];
    const float* w2 = (const float*)d_in[12];
    const float* g2 = (const float*)d_in[13];
    const float* b2 = (const float*)d_in[14];
    const float* m2 = (const float*)d_in[15];
    const float* v2 = (const float*)d_in[16];

    float* out = (float*)d_out;
    float* newxyz = out;                              // (B,S,3)
    float* newpts = out + (size_t)BATCH * SCENT * 3;  // (B,128,S)

    const int fps_smem = 3 * NPTS * 4;                              // 98304 B
    const int knn_smem = 3 * NPTS * 4;                              // 98304 B
    const int mlp_smem = (WF_TOTAL + 128 * MLP_Q_PER_CTA) * 4;      // 75776 B
    cudaFuncSetAttribute(fps_kernel, cudaFuncAttributeMaxDynamicSharedMemorySize, fps_smem);
    cudaFuncSetAttribute(knn_kernel, cudaFuncAttributeMaxDynamicSharedMemorySize, knn_smem);
    cudaFuncSetAttribute(mlp_kernel, cudaFuncAttributeMaxDynamicSharedMemorySize, mlp_smem);

    init_kernel<<<1, 32>>>();
    fold_kernel<<<1, 512>>>(w0, g0, b0, m0, v0, w1, g1, b1, m1, v1, w2, g2, b2, m2, v2);
    transpose_kernel<<<dim3(NPTS / 32, DFEAT / 32, BATCH), dim3(32, 8)>>>(points);
    fps_kernel<<<BATCH, 512, fps_smem>>>(xyz, newxyz);
    knn_kernel<<<BATCH * SCENT / 32, 1024, knn_smem>>>(xyz, newxyz);
    mlp_kernel<<<MLP_GRID, 256, mlp_smem>>>(xyz, newxyz, newpts);
}

// round 17
// speedup vs baseline: 1.1379x; 1.0038x over previous
#include <cuda_runtime.h>
#include <cuda_bf16.h>
#include <cstdint>

#define BATCH 4
#define NPTS 8192
#define DFEAT 64
#define SCENT 2048
#define KNEIGH 32
#define EPSBN 1e-5f

// ---------------- scratch (__device__ globals; no allocation allowed) ----------------
__device__ int   g_knn_idx[BATCH * SCENT * KNEIGH];          // 1 MB
__device__ float g_points_t[BATCH * NPTS * DFEAT];           // 8 MB  (B,N,64)
// folded weight blob, TRANSPOSED ([channel][output]) for paired-FMA2 access:
//  [0      .. 4352)  w0T: [c=0..67][o=0..63]   (c*64 + o), c=67 row is zero pad
//  [4352   .. 8448)  w1T: [c=0..63][o=0..63]   (4352 + c*64 + o)
//  [8448   ..16640)  w2T: [c=0..63][o=0..127]  (8448 + c*128 + o)
//  [16640  .. 16704) bias0 (64)
//  [16704  .. 16768) bias1 (64)
//  [16768  .. 16896) bias2 (128)
#define WF_TOTAL 16896
__device__ float g_wfold[WF_TOTAL];
// persistent-MLP work counter (reset every launch inside fold_kernel)
__device__ int g_mlp_ctr;

#define MLP_Q_PER_CTA 16
#define MLP_CHUNKS (BATCH * SCENT / MLP_Q_PER_CTA)   // 512
#define MLP_GRID 148

// ---------------- f32x2 helpers (bitwise-identical to scalar rn ops) ----------------
__device__ __forceinline__ unsigned long long pk2(float a, float b) {
    unsigned long long r;
    asm("mov.b64 %0, {%1, %2};" : "=l"(r) : "f"(a), "f"(b));
    return r;
}
__device__ __forceinline__ void unpk2(unsigned long long v, float& a, float& b) {
    asm("mov.b64 {%0, %1}, %2;" : "=f"(a), "=f"(b) : "l"(v));
}
__device__ __forceinline__ unsigned long long add2(unsigned long long a, unsigned long long b) {
    unsigned long long r;
    asm("add.rn.f32x2 %0, %1, %2;" : "=l"(r) : "l"(a), "l"(b));
    return r;
}
__device__ __forceinline__ unsigned long long mul2(unsigned long long a, unsigned long long b) {
    unsigned long long r;
    asm("mul.rn.f32x2 %0, %1, %2;" : "=l"(r) : "l"(a), "l"(b));
    return r;
}
__device__ __forceinline__ unsigned long long fma2(unsigned long long a, unsigned long long b,
                                                   unsigned long long c) {
    unsigned long long r;
    asm("fma.rn.f32x2 %0, %1, %2, %3;" : "=l"(r) : "l"(a), "l"(b), "l"(c));
    return r;
}

// ============================================================================
// Kernel 0a: fold BN into weights (transposed [c][o]) + reset MLP counter
// ============================================================================
__global__ void fold_kernel(const float* __restrict__ w0, const float* __restrict__ g0,
                            const float* __restrict__ b0, const float* __restrict__ m0,
                            const float* __restrict__ v0,
                            const float* __restrict__ w1, const float* __restrict__ g1,
                            const float* __restrict__ b1, const float* __restrict__ m1,
                            const float* __restrict__ v1,
                            const float* __restrict__ w2, const float* __restrict__ g2,
                            const float* __restrict__ b2, const float* __restrict__ m2,
                            const float* __restrict__ v2) {
    int tid = threadIdx.x, nt = blockDim.x;
    if (tid == 0) g_mlp_ctr = 0;   // deterministic graph replay
    for (int i = tid; i < 68 * 64; i += nt) {
        int c = i >> 6, o = i & 63;
        float s = g0[o] / sqrtf(v0[o] + EPSBN);
        g_wfold[c * 64 + o] = (c < 67) ? w0[o * 67 + c] * s : 0.0f;
    }
    for (int o = tid; o < 64; o += nt) {
        float s = g0[o] / sqrtf(v0[o] + EPSBN);
        g_wfold[16640 + o] = b0[o] - m0[o] * s;
    }
    for (int i = tid; i < 64 * 64; i += nt) {
        int c = i >> 6, o = i & 63;
        float s = g1[o] / sqrtf(v1[o] + EPSBN);
        g_wfold[4352 + c * 64 + o] = w1[o * 64 + c] * s;
    }
    for (int o = tid; o < 64; o += nt) {
        float s = g1[o] / sqrtf(v1[o] + EPSBN);
        g_wfold[16704 + o] = b1[o] - m1[o] * s;
    }
    for (int i = tid; i < 64 * 128; i += nt) {
        int c = i >> 7, o = i & 127;
        float s = g2[o] / sqrtf(v2[o] + EPSBN);
        g_wfold[8448 + c * 128 + o] = w2[o * 64 + c] * s;
    }
    for (int o = tid; o < 128; o += nt) {
        float s = g2[o] / sqrtf(v2[o] + EPSBN);
        g_wfold[16768 + o] = b2[o] - m2[o] * s;
    }
}

// ============================================================================
// Kernel 0b: transpose points (B,64,N) -> (B,N,64)
// ============================================================================
__global__ void transpose_kernel(const float* __restrict__ pts) {
    __shared__ float tl[32][33];
    int b = blockIdx.z;
    int dbase = blockIdx.y * 32;
    int nbase = blockIdx.x * 32;
    const float* src = pts + (size_t)b * DFEAT * NPTS;
    float* dst = g_points_t + (size_t)b * NPTS * DFEAT;
    int tx = threadIdx.x, ty = threadIdx.y;
#pragma unroll
    for (int r = ty; r < 32; r += 8)
        tl[r][tx] = src[(size_t)(dbase + r) * NPTS + nbase + tx];
    __syncthreads();
#pragma unroll
    for (int r = ty; r < 32; r += 8)
        dst[(size_t)(nbase + r) * DFEAT + dbase + tx] = tl[tx][r];
}

// ============================================================================
// Kernel 1: farthest point sampling — exact R6/R9/R16 winner (best measured):
// 512 threads x 16 strided pts, packed add2/mul2 distance math, scalar
// fminf/fmaxf, SMEM coords (no LDG on critical path), REDUX two-stage
// reduction, atomicMin tie-break, two barriers.
// rn mul/add via f32x2 (bitwise == scalar rn): trajectory bitwise == XLA.
// ============================================================================
__global__ void __launch_bounds__(512) fps_kernel(const float* __restrict__ xyz,
                                                  float* __restrict__ out_newxyz) {
    extern __shared__ float smf[];
    float* sxp = smf;              // [8192]
    float* syp = smf + NPTS;       // [8192]
    float* szp = smf + 2 * NPTS;   // [8192]
    const int b = blockIdx.x, t = threadIdx.x;
    const int lane = t & 31, wid = t >> 5;
    const float* px = xyz + (size_t)b * NPTS * 3;
    float* onx = out_newxyz + (size_t)b * SCENT * 3;

    unsigned long long Xp[8], Yp[8], Zp[8];
    float D[16];
#pragma unroll
    for (int p = 0; p < 8; p++) {
        int i0 = (2 * p) * 512 + t;
        int i1 = i0 + 512;
        float x0 = px[i0 * 3 + 0], y0 = px[i0 * 3 + 1], z0 = px[i0 * 3 + 2];
        float x1 = px[i1 * 3 + 0], y1 = px[i1 * 3 + 1], z1 = px[i1 * 3 + 2];
        sxp[i0] = x0; syp[i0] = y0; szp[i0] = z0;
        sxp[i1] = x1; syp[i1] = y1; szp[i1] = z1;
        Xp[p] = pk2(x0, x1);
        Yp[p] = pk2(y0, y1);
        Zp[p] = pk2(z0, z1);
        D[2 * p] = 1e10f;
        D[2 * p + 1] = 1e10f;
    }

    __shared__ unsigned s_wv[2][16];
    __shared__ int s_best[2];
    if (t == 0) { s_best[0] = 0x7fffffff; s_best[1] = 0x7fffffff; }
    __syncthreads();

    int far = 0;
    for (int it = 0; it < SCENT; ++it) {
        float cx = sxp[far];
        float cy = syp[far];
        float cz = szp[far];
        if (t == 0) {
            onx[it * 3 + 0] = cx;
            onx[it * 3 + 1] = cy;
            onx[it * 3 + 2] = cz;
        }
        unsigned long long ncx = pk2(-cx, -cx);
        unsigned long long ncy = pk2(-cy, -cy);
        unsigned long long ncz = pk2(-cz, -cz);

#pragma unroll
        for (int p = 0; p < 8; p++) {
            unsigned long long dx = add2(Xp[p], ncx);
            unsigned long long dy = add2(Yp[p], ncy);
            unsigned long long dz = add2(Zp[p], ncz);
            unsigned long long sx = mul2(dx, dx);
            unsigned long long sy = mul2(dy, dy);
            unsigned long long sz = mul2(dz, dz);
            unsigned long long dd = add2(add2(sx, sy), sz);
            float dlo, dhi;
            unpk2(dd, dlo, dhi);
            D[2 * p]     = fminf(D[2 * p], dlo);
            D[2 * p + 1] = fminf(D[2 * p + 1], dhi);
        }
        float lm = -1.0f;
#pragma unroll
        for (int k = 0; k < 16; k++) lm = fmaxf(lm, D[k]);

        // warp max via REDUX (distances >= 0 so uint order == float order)
        unsigned lmb = __float_as_uint(lm);
        unsigned wm = __reduce_max_sync(0xffffffffu, lmb);
        if (lane == 0) s_wv[it & 1][wid] = wm;
        __syncthreads();
        // every warp reduces the 16 leader values -> no serial warp0 phase
        unsigned gmb = __reduce_max_sync(0xffffffffu, s_wv[it & 1][lane & 15]);
        float gm = __uint_as_float(gmb);

        if (t == 0) s_best[(it + 1) & 1] = 0x7fffffff;  // reset next slot
        if (lmb == wm && wm == gmb) {
            int best = 0x7fffffff;
#pragma unroll
            for (int k = 15; k >= 0; k--)
                if (D[k] == gm) best = k * 512 + t;
            atomicMin(&s_best[it & 1], best);
        }
        __syncthreads();
        far = s_best[it & 1];
    }
}

// ============================================================================
// Kernel 2: KNN. One warp per query, 32 queries/CTA (1024 threads). Batch xyz
// in 96 KB SMEM as (x,y) float2 + z (LDS.64+LDS.32 per candidate instead of
// 3x LDS.32); candidate loop 2x unrolled (strict ascending order preserved ->
// identical tie behavior). Arithmetic identical to the R9 winner.
// ============================================================================
__device__ __forceinline__ void knn_scan32(
    int base, int lane,
    const float2* __restrict__ sxy, const float* __restrict__ szp,
    float qx, float qy, float qz,
    float& d, int& id, float& th)
{
    int jdx = base + lane;
    float2 xy = sxy[jdx];
    float zz = szp[jdx];
    float dx = qx - xy.x, dy = qy - xy.y, dz = qz - zz;
    float dj = fmaf(dx, dx, fmaf(dy, dy, dz * dz));
    unsigned mask = __ballot_sync(0xffffffffu, dj < th);
    while (mask) {
        int src = __ffs(mask) - 1;
        mask &= mask - 1;
        float dc = __shfl_sync(0xffffffffu, dj, src);
        int ic = base + src;
        if (dc < th) {
            float ud = __shfl_up_sync(0xffffffffu, d, 1);
            int ui = __shfl_up_sync(0xffffffffu, id, 1);
            bool gt = d > dc;
            bool ugt = (lane > 0) && (ud > dc);
            if (gt) {
                if (ugt) { d = ud; id = ui; }
                else     { d = dc; id = ic; }
            }
            th = __shfl_sync(0xffffffffu, d, 31);
        }
    }
}

__global__ void __launch_bounds__(1024) knn_kernel(const float* __restrict__ xyz,
                                                   const float* __restrict__ newxyz) {
    extern __shared__ float sm[];
    float2* sxy = (float2*)sm;          // [8192] (x,y)
    float* szp = sm + 2 * NPTS;         // [8192] z
    const int b = blockIdx.x >> 6;              // 64 CTAs per batch
    const int sbase = (blockIdx.x & 63) * 32;   // 32 queries per CTA
    const float* px = xyz + (size_t)b * NPTS * 3;

    for (int i = threadIdx.x; i < NPTS; i += 1024) {
        float x = px[3 * i], y = px[3 * i + 1], z = px[3 * i + 2];
        sxy[i] = make_float2(x, y);
        szp[i] = z;
    }
    __syncthreads();

    const int lane = threadIdx.x & 31, wid = threadIdx.x >> 5;
    const int g = b * SCENT + sbase + wid;
    const float qx = newxyz[3 * g], qy = newxyz[3 * g + 1], qz = newxyz[3 * g + 2];

    float d;
    int id;
    {
        float2 xy = sxy[lane];
        float zz = szp[lane];
        float dx = qx - xy.x, dy = qy - xy.y, dz = qz - zz;
        d = fmaf(dx, dx, fmaf(dy, dy, dz * dz));
        id = lane;
    }
    // bitonic sort ascending across warp
#pragma unroll
    for (int k = 2; k <= 32; k <<= 1) {
#pragma unroll
        for (int jj = k >> 1; jj; jj >>= 1) {
            float od = __shfl_xor_sync(0xffffffffu, d, jj);
            int oi = __shfl_xor_sync(0xffffffffu, id, jj);
            bool up = ((lane & k) == 0);
            bool lower = ((lane & jj) == 0);
            bool take = lower ? (up ? (od < d) : (od > d)) : (up ? (od > d) : (od < d));
            if (take) { d = od; id = oi; }
        }
    }
    float th = __shfl_sync(0xffffffffu, d, 31);

    // candidates 32..63 (single block), then 2x-unrolled from 64
    knn_scan32(32, lane, sxy, szp, qx, qy, qz, d, id, th);
    for (int base = 64; base < NPTS; base += 64) {
        knn_scan32(base, lane, sxy, szp, qx, qy, qz, d, id, th);
        knn_scan32(base + 32, lane, sxy, szp, qx, qy, qz, d, id, th);
    }
    g_knn_idx[(size_t)g * KNEIGH + lane] = id;
}

// ============================================================================
// Kernel 3: PERSISTENT gather + fused MLP(67->64->64->128) + max over K.
// Grid = 148 CTAs; chunks of 16 queries via atomicAdd counter. Body numerics
// identical to R16 winner (chunk output is assignment-invariant).
// ============================================================================
__global__ void __launch_bounds__(256) mlp_kernel(const float* __restrict__ xyz,
                                                  const float* __restrict__ newxyz,
                                                  float* __restrict__ outp) {
    extern __shared__ float sm[];
    {
        const float4* srcv = (const float4*)g_wfold;
        float4* dstv = (float4*)sm;
        for (int i = threadIdx.x; i < WF_TOTAL / 4; i += 256) dstv[i] = srcv[i];
    }
    float* otile = sm + WF_TOTAL;  // [128][16]
    __shared__ int s_chunk;
    __syncthreads();

    const int lane = threadIdx.x & 31, wid = threadIdx.x >> 5;

    while (true) {
        if (threadIdx.x == 0) s_chunk = atomicAdd(&g_mlp_ctr, 1);
        __syncthreads();
        const int mb = s_chunk;
        if (mb >= MLP_CHUNKS) break;

#pragma unroll 1
        for (int j = 0; j < 2; j++) {
            const int qc = wid * 2 + j;
            const int g = mb * MLP_Q_PER_CTA + qc;
            const int b = g >> 11;
            const float qx = newxyz[3 * g], qy = newxyz[3 * g + 1], qz = newxyz[3 * g + 2];

            const int n = g_knn_idx[(size_t)g * KNEIGH + lane];
            const float* p = xyz + ((size_t)b * NPTS + n) * 3;

            float in0[68];
            in0[0] = p[0] - qx;
            in0[1] = p[1] - qy;
            in0[2] = p[2] - qz;
            const float4* fr = (const float4*)(g_points_t + ((size_t)b * NPTS + n) * DFEAT);
#pragma unroll
            for (int c = 0; c < 16; c++) {
                float4 v = __ldg(fr + c);
                in0[3 + 4 * c] = v.x;
                in0[4 + 4 * c] = v.y;
                in0[5 + 4 * c] = v.z;
                in0[6 + 4 * c] = v.w;
            }
            in0[67] = 0.0f;

            unsigned long long acc[32];

            // ---- layer 0: 68 channels (incl. zero pad) -> 64 outputs ----
#pragma unroll
            for (int o2 = 0; o2 < 32; o2++)
                acc[o2] = *(const unsigned long long*)(sm + 16640 + 2 * o2);
#pragma unroll
            for (int c = 0; c < 68; c++) {
                unsigned long long inp = pk2(in0[c], in0[c]);
                const ulonglong2* wrow = (const ulonglong2*)(sm + c * 64);
#pragma unroll
                for (int gq = 0; gq < 16; gq++) {
                    ulonglong2 w = wrow[gq];
                    acc[2 * gq]     = fma2(inp, w.x, acc[2 * gq]);
                    acc[2 * gq + 1] = fma2(inp, w.y, acc[2 * gq + 1]);
                }
            }
            float h1[64];
#pragma unroll
            for (int o2 = 0; o2 < 32; o2++) {
                float lo, hi;
                unpk2(acc[o2], lo, hi);
                h1[2 * o2] = fmaxf(lo, 0.0f);
                h1[2 * o2 + 1] = fmaxf(hi, 0.0f);
            }

            // ---- layer 1: 64 -> 64 ----
#pragma unroll
            for (int o2 = 0; o2 < 32; o2++)
                acc[o2] = *(const unsigned long long*)(sm + 16704 + 2 * o2);
#pragma unroll
            for (int c = 0; c < 64; c++) {
                unsigned long long inp = pk2(h1[c], h1[c]);
                const ulonglong2* wrow = (const ulonglong2*)(sm + 4352 + c * 64);
#pragma unroll
                for (int gq = 0; gq < 16; gq++) {
                    ulonglong2 w = wrow[gq];
                    acc[2 * gq]     = fma2(inp, w.x, acc[2 * gq]);
                    acc[2 * gq + 1] = fma2(inp, w.y, acc[2 * gq + 1]);
                }
            }
            float h2[64];
#pragma unroll
            for (int o2 = 0; o2 < 32; o2++) {
                float lo, hi;
                unpk2(acc[o2], lo, hi);
                h2[2 * o2] = fmaxf(lo, 0.0f);
                h2[2 * o2 + 1] = fmaxf(hi, 0.0f);
            }

            // ---- layer 2: 64 -> 128, two halves of 64 outputs ----
#pragma unroll 1
            for (int h = 0; h < 2; h++) {
#pragma unroll
                for (int o2 = 0; o2 < 32; o2++)
                    acc[o2] = *(const unsigned long long*)(sm + 16768 + h * 64 + 2 * o2);
#pragma unroll
                for (int c = 0; c < 64; c++) {
                    unsigned long long inp = pk2(h2[c], h2[c]);
                    const ulonglong2* wrow = (const ulonglong2*)(sm + 8448 + c * 128 + h * 64);
#pragma unroll
                    for (int gq = 0; gq < 16; gq++) {
                        ulonglong2 w = wrow[gq];
                        acc[2 * gq]     = fma2(inp, w.x, acc[2 * gq]);
                        acc[2 * gq + 1] = fma2(inp, w.y, acc[2 * gq + 1]);
                    }
                }
#pragma unroll
                for (int o2 = 0; o2 < 32; o2++) {
                    float lo, hi;
                    unpk2(acc[o2], lo, hi);
                    float rlo = fmaxf(lo, 0.0f);
                    float rhi = fmaxf(hi, 0.0f);
                    // post-ReLU >= 0: uint order == float order
                    unsigned ulo = __reduce_max_sync(0xffffffffu, __float_as_uint(rlo));
                    unsigned uhi = __reduce_max_sync(0xffffffffu, __float_as_uint(rhi));
                    if (lane == 0) {
                        otile[(h * 64 + 2 * o2) * MLP_Q_PER_CTA + qc] = __uint_as_float(ulo);
                        otile[(h * 64 + 2 * o2 + 1) * MLP_Q_PER_CTA + qc] = __uint_as_float(uhi);
                    }
                }
            }
        }
        __syncthreads();
        const int g0 = mb * MLP_Q_PER_CTA;
        const int b = g0 >> 11;
        const int sbase = g0 & 2047;
        for (int i = threadIdx.x; i < 128 * MLP_Q_PER_CTA; i += 256) {
            int o = i / MLP_Q_PER_CTA, qc = i - o * MLP_Q_PER_CTA;
            outp[((size_t)b * 128 + o) * SCENT + sbase + qc] = otile[i];
        }
        __syncthreads();  // otile reused next chunk
    }
}

// ============================================================================
// Launch
// ============================================================================
extern "C" void kernel_launch(void* const* d_in, const int* in_sizes, int n_in,
                              void* d_out, int out_size) {
    const float* xyz = (const float*)d_in[0];
    const float* points = (const float*)d_in[1];
    const float* w0 = (const float*)d_in[2];
    const float* g0 = (const float*)d_in[3];
    const float* b0 = (const float*)d_in[4];
    const float* m0 = (const float*)d_in[5];
    const float* v0 = (const float*)d_in[6];
    const float* w1 = (const float*)d_in[7];
    const float* g1 = (const float*)d_in[8];
    const float* b1 = (const float*)d_in[9];
    const float* m1 = (const float*)d_in[10];
    const float* v1 = (const float*)d_in[11];
    const float* w2 = (const float*)d_in[12];
    const float* g2 = (const float*)d_in[13];
    const float* b2 = (const float*)d_in[14];
    const float* m2 = (const float*)d_in[15];
    const float* v2 = (const float*)d_in[16];

    float* out = (float*)d_out;
    float* newxyz = out;                              // (B,S,3)
    float* newpts = out + (size_t)BATCH * SCENT * 3;  // (B,128,S)

    const int fps_smem = 3 * NPTS * 4;                              // 98304 B
    const int knn_smem = 3 * NPTS * 4;                              // 98304 B
    const int mlp_smem = (WF_TOTAL + 128 * MLP_Q_PER_CTA) * 4;      // 75776 B
    cudaFuncSetAttribute(fps_kernel, cudaFuncAttributeMaxDynamicSharedMemorySize, fps_smem);
    cudaFuncSetAttribute(knn_kernel, cudaFuncAttributeMaxDynamicSharedMemorySize, knn_smem);
    cudaFuncSetAttribute(mlp_kernel, cudaFuncAttributeMaxDynamicSharedMemorySize, mlp_smem);

    fold_kernel<<<1, 512>>>(w0, g0, b0, m0, v0, w1, g1, b1, m1, v1, w2, g2, b2, m2, v2);
    transpose_kernel<<<dim3(NPTS / 32, DFEAT / 32, BATCH), dim3(32, 8)>>>(points);
    fps_kernel<<<BATCH, 512, fps_smem>>>(xyz, newxyz);
    knn_kernel<<<BATCH * SCENT / 32, 1024, knn_smem>>>(xyz, newxyz);
    mlp_kernel<<<MLP_GRID, 256, mlp_smem>>>(xyz, newxyz, newpts);
}